// round 6
// baseline (speedup 1.0000x reference)
#include <cuda_runtime.h>
#include <math.h>

// Problem constants (match reference)
#define BB 8
#define HH 256
#define WW 256
#define XT 8                      // x-columns per block
#define NBLK (BB * (WW / XT))     // 256 blocks
#define KWIN 4                    // column window radius (exactness-checked)
#define TROWS (HH + 2 * KWIN)     // padded tile rows (264)

// ---------------------------------------------------------------------------
// Scratch (device globals — no allocation allowed)
// ---------------------------------------------------------------------------
__device__ double d_partials[NBLK][4];   // {sum p*dist, sum p*t, sum p*p, sum t*t}
__device__ int g_fin;                    // finalize election counter (self-resetting)

// Exact distance to nearest set (inv=false) / clear (inv=true) bit in a
// 256-bit row mask, from position i. Sentinel 1000 -> squared 1e10 == ref INF.
// Fallback-only.
__device__ __forceinline__ int exact_dist(const unsigned* m, int i, bool inv) {
    const int wi = i >> 5, bi = i & 31;
    const unsigned mw = inv ? ~m[wi] : m[wi];
    const unsigned lowmask = (2u << bi) - 1u;
    const unsigned himask  = ~((1u << bi) - 1u);
    unsigned wl = mw & lowmask;
    int dl = 100000;
    if (wl) dl = bi - (31 - __clz(wl));
    else {
        for (int k = wi - 1; k >= 0; --k) {
            const unsigned mk = inv ? ~m[k] : m[k];
            if (mk) { dl = i - (k * 32 + 31 - __clz(mk)); break; }
        }
    }
    unsigned wr = mw & himask;
    int dr = 100000;
    if (wr) dr = (__ffs(wr) - 1) - bi;
    else {
        for (int k = wi + 1; k < 8; ++k) {
            const unsigned mk = inv ? ~m[k] : m[k];
            if (mk) { dr = (k * 32 + __ffs(mk) - 1) - i; break; }
        }
    }
    return min(min(dl, dr), 1000);
}

// ---------------------------------------------------------------------------
// ONE kernel, ONE phase, no grid barrier. Block = 8 columns of one image;
// thread = one row. Row-distances (clamped at 6) decoded from a register-held
// 24-bit strip of target; windowed column min-plus (K=4) with exactness check
// and an exact full fallback; fused sigmoid + dice/boundary partials;
// last-block deterministic finalize.
// ---------------------------------------------------------------------------
__global__ __launch_bounds__(HH) void fused(const float* __restrict__ pred,
                                            const float* __restrict__ target,
                                            const int* __restrict__ fl_ptr,
                                            float* __restrict__ out) {
    const int blk  = blockIdx.x;
    const int tid  = threadIdx.x;
    const int warp = tid >> 5;
    const int lane = tid & 31;

    const int b  = blk >> 5;           // image
    const int x0 = (blk & 31) * XT;    // first column (multiple of 8)
    const int base = b * HH * WW;

    __shared__ __align__(16) float sa[TROWS][XT];  // dist^2 to nearest 1 (clamped)
    __shared__ __align__(16) float sb[TROWS][XT];  // dist^2 to nearest 0 (clamped)
    __shared__ unsigned smask[HH * 8];             // fallback-only row masks
    __shared__ float rs[8][4];
    __shared__ double fg[8][2];
    __shared__ int s_last;

    // Sentinel rows (never win a min).
    if (tid < 8) {
        const int ry = (tid < 4) ? tid : (TROWS - 8 + tid);
        const float4 s4 = make_float4(1e18f, 1e18f, 1e18f, 1e18f);
        *reinterpret_cast<float4*>(&sa[ry][0]) = s4;
        *reinterpret_cast<float4*>(&sa[ry][4]) = s4;
        *reinterpret_cast<float4*>(&sb[ry][0]) = s4;
        *reinterpret_cast<float4*>(&sb[ry][4]) = s4;
    }

    // ---- per-thread: load 24-col strip of my row, build bitmask, distances --
    const int y = tid;                 // my image row
    {
        // Strip columns [x0-8, x0+15]; each float4 chunk fully in or out.
        float vals[24];
#pragma unroll
        for (int k = 0; k < 6; ++k) {
            const int cx = x0 - 8 + k * 4;
            float4 v4;
            if (cx >= 0 && cx <= WW - 4)
                v4 = *reinterpret_cast<const float4*>(&target[base + y * WW + cx]);
            else
                v4 = make_float4(0.f, 0.f, 0.f, 0.f);
            vals[k * 4 + 0] = v4.x; vals[k * 4 + 1] = v4.y;
            vals[k * 4 + 2] = v4.z; vals[k * 4 + 3] = v4.w;
        }
        unsigned M = 0;
#pragma unroll
        for (int k = 0; k < 24; ++k) M |= (vals[k] > 0.5f ? 1u : 0u) << k;

        const int ry = y + KWIN;
        float da[XT], db[XT];
#pragma unroll
        for (int c = 0; c < XT; ++c) {
            const int x = x0 + c;
            // window bits: offsets -5..+5 around x  (strip bit of x is c+8)
            const unsigned win = (M >> (c + 3)) & 0x7FFu;
            unsigned vm = 0x7FFu;
            if (x < 5)   vm &= (0x7FFu << (5 - x));
            if (x > 250) vm &= (0x7FFu >> (x - 250));
            // nearest 1
            unsigned wm = win & vm;
            unsigned l = wm & 0x1Fu, r = wm >> 6;
            int dl = __clz(l) - 26;                 // l==0 -> 6
            int fr = __ffs(r); int dr = fr ? fr : 6;
            const int d1 = (wm & 0x20u) ? 0 : min(dl, dr);
            // nearest 0
            wm = (~win) & vm;
            l = wm & 0x1Fu; r = wm >> 6;
            dl = __clz(l) - 26;
            fr = __ffs(r); dr = fr ? fr : 6;
            const int d0 = (wm & 0x20u) ? 0 : min(dl, dr);
            da[c] = (float)(d1 * d1);               // 36 == "clamped >=6"
            db[c] = (float)(d0 * d0);
        }
        *reinterpret_cast<float4*>(&sa[ry][0]) = make_float4(da[0], da[1], da[2], da[3]);
        *reinterpret_cast<float4*>(&sa[ry][4]) = make_float4(da[4], da[5], da[6], da[7]);
        *reinterpret_cast<float4*>(&sb[ry][0]) = make_float4(db[0], db[1], db[2], db[3]);
        *reinterpret_cast<float4*>(&sb[ry][4]) = make_float4(db[4], db[5], db[6], db[7]);
    }
    __syncthreads();

    // ---------------- windowed column min-plus -----------------------------
    float aa[XT], ab[XT];
#pragma unroll
    for (int c = 0; c < XT; ++c) { aa[c] = 3.0e38f; ab[c] = 3.0e38f; }
#pragma unroll
    for (int dj = -KWIN; dj <= KWIN; ++dj) {
        const float d2 = (float)(dj * dj);
        const int si = y + dj + KWIN;
        const float4 va0 = *reinterpret_cast<const float4*>(&sa[si][0]);
        const float4 va1 = *reinterpret_cast<const float4*>(&sa[si][4]);
        const float4 vb0 = *reinterpret_cast<const float4*>(&sb[si][0]);
        const float4 vb1 = *reinterpret_cast<const float4*>(&sb[si][4]);
        aa[0] = fminf(aa[0], va0.x + d2); aa[1] = fminf(aa[1], va0.y + d2);
        aa[2] = fminf(aa[2], va0.z + d2); aa[3] = fminf(aa[3], va0.w + d2);
        aa[4] = fminf(aa[4], va1.x + d2); aa[5] = fminf(aa[5], va1.y + d2);
        aa[6] = fminf(aa[6], va1.z + d2); aa[7] = fminf(aa[7], va1.w + d2);
        ab[0] = fminf(ab[0], vb0.x + d2); ab[1] = fminf(ab[1], vb0.y + d2);
        ab[2] = fminf(ab[2], vb0.z + d2); ab[3] = fminf(ab[3], vb0.w + d2);
        ab[4] = fminf(ab[4], vb1.x + d2); ab[5] = fminf(ab[5], vb1.y + d2);
        ab[6] = fminf(ab[6], vb1.z + d2); ab[7] = fminf(ab[7], vb1.w + d2);
    }

    // Exactness: clamped row-dists / outside-window candidates all exceed
    // (K+1)^2 = 25 -> if any windowed min > 25, redo the block exactly.
    float mymax = 0.0f;
#pragma unroll
    for (int c = 0; c < XT; ++c) mymax = fmaxf(mymax, fmaxf(aa[c], ab[c]));
    const int need_full = __syncthreads_or(mymax > 25.0f);
    if (need_full) {
        // Build full row masks in smem (shared atomics; fallback-only).
        for (int e = tid; e < HH * 8; e += HH) smask[e] = 0u;
        __syncthreads();
        for (int idx = tid; idx < HH * WW; idx += HH) {
            if (target[base + idx] > 0.5f)
                atomicOr(&smask[idx >> 5], 1u << (idx & 31));
        }
        __syncthreads();
        // Exact unclamped tile rebuild.
        {
            const unsigned* wr = &smask[y * 8];
#pragma unroll
            for (int c = 0; c < XT; ++c) {
                const int x = x0 + c;
                const int d1 = exact_dist(wr, x, false);
                const int d0 = exact_dist(wr, x, true);
                sa[y + KWIN][c] = (d1 >= 1000) ? 1e10f : (float)(d1 * d1);
                sb[y + KWIN][c] = (d0 >= 1000) ? 1e10f : (float)(d0 * d0);
            }
        }
        __syncthreads();
#pragma unroll
        for (int c = 0; c < XT; ++c) { aa[c] = 3.0e38f; ab[c] = 3.0e38f; }
        float d = (float)y;
        for (int j = 0; j < HH; ++j) {
            const float d2 = d * d;
            d -= 1.0f;
            const float4 va0 = *reinterpret_cast<const float4*>(&sa[j + KWIN][0]);
            const float4 va1 = *reinterpret_cast<const float4*>(&sa[j + KWIN][4]);
            const float4 vb0 = *reinterpret_cast<const float4*>(&sb[j + KWIN][0]);
            const float4 vb1 = *reinterpret_cast<const float4*>(&sb[j + KWIN][4]);
            aa[0] = fminf(aa[0], va0.x + d2); aa[1] = fminf(aa[1], va0.y + d2);
            aa[2] = fminf(aa[2], va0.z + d2); aa[3] = fminf(aa[3], va0.w + d2);
            aa[4] = fminf(aa[4], va1.x + d2); aa[5] = fminf(aa[5], va1.y + d2);
            aa[6] = fminf(aa[6], va1.z + d2); aa[7] = fminf(aa[7], va1.w + d2);
            ab[0] = fminf(ab[0], vb0.x + d2); ab[1] = fminf(ab[1], vb0.y + d2);
            ab[2] = fminf(ab[2], vb0.z + d2); ab[3] = fminf(ab[3], vb0.w + d2);
            ab[4] = fminf(ab[4], vb1.x + d2); ab[5] = fminf(ab[5], vb1.y + d2);
            ab[6] = fminf(ab[6], vb1.z + d2); ab[7] = fminf(ab[7], vb1.w + d2);
        }
    }

    // ---------------- epilogue: sigmoid + partial sums ---------------------
    const int fl = *fl_ptr;
    const int gidx = base + y * WW + x0;
    float pvals[XT], tvals[XT];
    {
        const float4 p0 = *reinterpret_cast<const float4*>(&pred[gidx]);
        const float4 p1 = *reinterpret_cast<const float4*>(&pred[gidx + 4]);
        const float4 t0 = *reinterpret_cast<const float4*>(&target[gidx]);
        const float4 t1 = *reinterpret_cast<const float4*>(&target[gidx + 4]);
        pvals[0] = p0.x; pvals[1] = p0.y; pvals[2] = p0.z; pvals[3] = p0.w;
        pvals[4] = p1.x; pvals[5] = p1.y; pvals[6] = p1.z; pvals[7] = p1.w;
        tvals[0] = t0.x; tvals[1] = t0.y; tvals[2] = t0.z; tvals[3] = t0.w;
        tvals[4] = t1.x; tvals[5] = t1.y; tvals[6] = t1.z; tvals[7] = t1.w;
    }

    float s_pd = 0.0f, s_pt = 0.0f, s_pp = 0.0f, s_tt = 0.0f;
#pragma unroll
    for (int k = 0; k < XT; ++k) {
        float p = pvals[k];
        if (fl) p = __fdividef(1.0f, 1.0f + __expf(-p));
        const float dist = sqrtf(aa[k]) + sqrtf(ab[k]);
        s_pd += p * dist;
        s_pt += p * tvals[k];
        s_pp += p * p;
        s_tt += tvals[k] * tvals[k];
    }

#pragma unroll
    for (int off = 16; off > 0; off >>= 1) {
        s_pd += __shfl_down_sync(0xffffffffu, s_pd, off);
        s_pt += __shfl_down_sync(0xffffffffu, s_pt, off);
        s_pp += __shfl_down_sync(0xffffffffu, s_pp, off);
        s_tt += __shfl_down_sync(0xffffffffu, s_tt, off);
    }
    if (lane == 0) {
        rs[warp][0] = s_pd; rs[warp][1] = s_pt;
        rs[warp][2] = s_pp; rs[warp][3] = s_tt;
    }
    __syncthreads();

    if (tid == 0) {
        double a0 = 0.0, a1 = 0.0, a2 = 0.0, a3 = 0.0;
#pragma unroll
        for (int w = 0; w < 8; ++w) {
            a0 += (double)rs[w][0]; a1 += (double)rs[w][1];
            a2 += (double)rs[w][2]; a3 += (double)rs[w][3];
        }
        d_partials[blk][0] = a0; d_partials[blk][1] = a1;
        d_partials[blk][2] = a2; d_partials[blk][3] = a3;
        __threadfence();
        const int old = atomicAdd(&g_fin, 1);
        s_last = (old == NBLK - 1);
    }
    __syncthreads();
    if (!s_last) return;

    // ---------------- last block: deterministic finalize -------------------
    __threadfence();
    {
        const int g = warp;                   // one warp per image (8 images)
        const int s = g * 32 + lane;          // 32 partials per image
        double v0 = d_partials[s][0];
        double v1 = d_partials[s][1];
        double v2 = d_partials[s][2];
        double v3 = d_partials[s][3];
#pragma unroll
        for (int off = 16; off > 0; off >>= 1) {
            v0 += __shfl_down_sync(0xffffffffu, v0, off);
            v1 += __shfl_down_sync(0xffffffffu, v1, off);
            v2 += __shfl_down_sync(0xffffffffu, v2, off);
            v3 += __shfl_down_sync(0xffffffffu, v3, off);
        }
        if (lane == 0) {
            const double eps = 1e-6;
            fg[g][0] = v0;                                        // boundary sum
            fg[g][1] = 1.0 - (2.0 * v1 + eps) / (v2 + v3 + eps);  // dice term
        }
    }
    __syncthreads();
    if (tid == 0) {
        double bl = 0.0, dl = 0.0;
#pragma unroll
        for (int g = 0; g < BB; ++g) { bl += fg[g][0]; dl += fg[g][1]; }
        dl /= (double)BB;
        bl /= (double)(BB * HH * WW);
        out[0] = (float)(dl + bl);  // ALPHA = BETA = 1
        g_fin = 0;                  // reset for next (graph) replay
        __threadfence();
    }
}

// ---------------------------------------------------------------------------
extern "C" void kernel_launch(void* const* d_in, const int* in_sizes, int n_in,
                              void* d_out, int out_size) {
    const float* pred   = (const float*)d_in[0];
    const float* target = (const float*)d_in[1];
    const int*   fl     = (const int*)d_in[2];
    float* out = (float*)d_out;

    fused<<<NBLK, HH>>>(pred, target, fl, out);
}